// round 1
// baseline (speedup 1.0000x reference)
#include <cuda_runtime.h>

#define NQ      22
#define NSTATE  (1u << NQ)
#define NLAYERS 8

// Ping-pong statevector buffers (64 MB total; fits in L2 alongside nothing else hot)
__device__ float2 g_state[2][NSTATE];
// Fused single-qubit unitaries U = RX*RZ*RY, per layer per qubit, row-major [u00,u01,u10,u11]
__device__ float2 g_U[NLAYERS][NQ][4];
// Product-state tables for layer 0: amp(g) = Phi[g>>11] * Plo[g & 0x7FF]
__device__ float2 g_Phi[2048];
__device__ float2 g_Plo[2048];

__device__ __forceinline__ float2 cmul(float2 a, float2 b) {
    return make_float2(a.x * b.x - a.y * b.y, a.x * b.y + a.y * b.x);
}
__device__ __forceinline__ float2 cfma(float2 u, float2 x, float2 acc) {
    acc.x = fmaf(u.x, x.x, acc.x);
    acc.x = fmaf(-u.y, x.y, acc.x);
    acc.y = fmaf(u.x, x.y, acc.y);
    acc.y = fmaf(u.y, x.x, acc.y);
    return acc;
}

// ---------------------------------------------------------------------------
// Prep: compute fused U matrices for all layers, then layer-0 product tables.
// ---------------------------------------------------------------------------
__global__ void prep_kernel(const float* __restrict__ p) {
    int tid = threadIdx.x;
    if (tid < NLAYERS * NQ) {
        int l = tid / NQ, q = tid % NQ;
        float ty = p[l * 3 * NQ + q];
        float tz = p[l * 3 * NQ + NQ + q];
        float tx = p[l * 3 * NQ + 2 * NQ + q];
        float cy = cosf(0.5f * ty), sy = sinf(0.5f * ty);
        float cz = cosf(0.5f * tz), sz = sinf(0.5f * tz);
        float cx = cosf(0.5f * tx), sx = sinf(0.5f * tx);
        float2 em = make_float2(cz, -sz);   // e^{-i tz/2}
        float2 ep = make_float2(cz, sz);    // e^{+i tz/2}
        // U = RX(tx) * RZ(tz) * RY(ty)
        // U00 =  cx*cy*em - i*sx*sy*ep
        float2 u00 = make_float2(cx * cy * em.x + sx * sy * ep.y,
                                 cx * cy * em.y - sx * sy * ep.x);
        // U01 = -cx*sy*em - i*sx*cy*ep
        float2 u01 = make_float2(-cx * sy * em.x + sx * cy * ep.y,
                                 -cx * sy * em.y - sx * cy * ep.x);
        // U10 = -i*sx*cy*em + cx*sy*ep
        float2 u10 = make_float2(sx * cy * em.y + cx * sy * ep.x,
                                 -sx * cy * em.x + cx * sy * ep.y);
        // U11 =  i*sx*sy*em + cx*cy*ep
        float2 u11 = make_float2(-sx * sy * em.y + cx * cy * ep.x,
                                 sx * sy * em.x + cx * cy * ep.y);
        g_U[l][q][0] = u00; g_U[l][q][1] = u01;
        g_U[l][q][2] = u10; g_U[l][q][3] = u11;
    }
    __syncthreads();
    // Layer-0 product tables: state0[g] = prod_q U0[q][bit_{21-q}(g)][0]
    for (int i = tid; i < 2048; i += blockDim.x) {
        float2 ph = make_float2(1.f, 0.f);
        float2 pl = make_float2(1.f, 0.f);
        for (int q = 0; q <= 10; q++) {
            int b = (i >> (10 - q)) & 1;             // bit 21-q of g maps to bit (10-q) of hi-chunk
            ph = cmul(ph, g_U[0][q][b * 2]);
        }
        for (int q = 11; q <= 21; q++) {
            int b = (i >> (21 - q)) & 1;
            pl = cmul(pl, g_U[0][q][b * 2]);
        }
        g_Phi[i] = ph;
        g_Plo[i] = pl;
    }
}

// ---------------------------------------------------------------------------
// L kernel: bits 0..10 local (2048 contiguous amps). Applies qubits 11..21.
// Load applies previous layer's CNOT chain via Gray-code addressing
// (src index = t ^ (t>>1)); for layer 1, synthesizes the layer-0 state.
// ---------------------------------------------------------------------------
__global__ void __launch_bounds__(256) kernelL(int layer, int srcIdx, int dstIdx, int first) {
    __shared__ __align__(16) float2 sh[2048];
    const int tid = threadIdx.x;
    const unsigned h   = blockIdx.x;           // bits 11..21 of target index
    const unsigned ghi = h ^ (h >> 1);         // high bits of Gray(t)
    const unsigned c10 = (h & 1u) << 10;       // carry of Gray into bit 10
    const unsigned base  = h << 11;
    const unsigned gbase = ghi << 11;

    if (first) {
        const float2 ph = g_Phi[ghi];
        for (int l = tid; l < 2048; l += 256) {
            unsigned glo = (l ^ (l >> 1)) ^ c10;
            sh[l] = cmul(ph, g_Plo[glo]);
        }
    } else {
        const float2* __restrict__ src = g_state[srcIdx];
        for (int l = tid; l < 2048; l += 256) {
            unsigned glo = (l ^ (l >> 1)) ^ c10;
            sh[l] = src[gbase + glo];
        }
    }
    __syncthreads();

    for (int b = 0; b < 11; b++) {
        const int q = 21 - b;                  // qubit acted on (bit b = bit 21-q)
        const float2 u00 = g_U[layer][q][0];
        const float2 u01 = g_U[layer][q][1];
        const float2 u10 = g_U[layer][q][2];
        const float2 u11 = g_U[layer][q][3];
        if (b == 0) {
            // adjacent pairs: vectorize as float4 (conflict-free LDS.128)
            float4* sh4 = reinterpret_cast<float4*>(sh);
            for (int pr = tid; pr < 1024; pr += 256) {
                float4 v = sh4[pr];
                float2 x = make_float2(v.x, v.y);
                float2 y = make_float2(v.z, v.w);
                float2 o0 = cfma(u01, y, cmul(u00, x));
                float2 o1 = cfma(u11, y, cmul(u10, x));
                sh4[pr] = make_float4(o0.x, o0.y, o1.x, o1.y);
            }
        } else {
            const int mask = (1 << b) - 1;
            for (int pr = tid; pr < 1024; pr += 256) {
                int j0 = ((pr >> b) << (b + 1)) | (pr & mask);
                int j1 = j0 | (1 << b);
                float2 x = sh[j0], y = sh[j1];
                sh[j0] = cfma(u01, y, cmul(u00, x));
                sh[j1] = cfma(u11, y, cmul(u10, x));
            }
        }
        __syncthreads();
    }

    float2* __restrict__ dst = g_state[dstIdx];
    float4* dst4 = reinterpret_cast<float4*>(dst + base);
    const float4* sh4 = reinterpret_cast<const float4*>(sh);
    for (int l = tid; l < 1024; l += 256) dst4[l] = sh4[l];
}

// ---------------------------------------------------------------------------
// H kernel: gate bits 11..21 + coalesce bits 0..1 local (8192 amps, 64 KB).
// Applies qubits 0..10. Optionally folds final CNOT chain + |amp|^2 into the
// store via inverse-Gray scatter (probs != nullptr).
// ---------------------------------------------------------------------------
__global__ void __launch_bounds__(256) kernelH(int layer, int srcIdx, int dstIdx,
                                               float* __restrict__ probs) {
    extern __shared__ float4 sh4h[];
    float2* shh = reinterpret_cast<float2*>(sh4h);
    const int tid = threadIdx.x;
    const unsigned f = blockIdx.x;             // bits 2..10 of global index

    {   // load: global = (v<<11)|(f<<2)|c  ->  local i = (v<<2)|c ; float4 over c-pairs
        const float4* __restrict__ src4 = reinterpret_cast<const float4*>(g_state[srcIdx]);
        for (int i2 = tid; i2 < 4096; i2 += 256) {
            unsigned v = i2 >> 1, cp = i2 & 1;
            sh4h[i2] = src4[(v << 10) | (f << 1) | cp];
        }
    }
    __syncthreads();

    for (int k = 0; k < 11; k++) {
        const int q  = 10 - k;                 // global bit B = 11+k  ->  qubit 21-B = 10-k
        const int lb = k + 2;                  // local bit within tile
        const float2 u00 = g_U[layer][q][0];
        const float2 u01 = g_U[layer][q][1];
        const float2 u10 = g_U[layer][q][2];
        const float2 u11 = g_U[layer][q][3];
        const int mask = (1 << lb) - 1;
        for (int pr = tid; pr < 4096; pr += 256) {
            int j0 = ((pr >> lb) << (lb + 1)) | (pr & mask);
            int j1 = j0 | (1 << lb);
            float2 x = shh[j0], y = shh[j1];
            shh[j0] = cfma(u01, y, cmul(u00, x));
            shh[j1] = cfma(u11, y, cmul(u10, x));
        }
        __syncthreads();
    }

    if (probs) {
        // apply final CNOT chain as forward map t = prefix-XOR(j), write |amp|^2
        for (int i = tid; i < 8192; i += 256) {
            unsigned v = i >> 2, c = i & 3;
            unsigned j = (v << 11) | (f << 2) | c;
            unsigned t = j;
            t ^= t >> 1; t ^= t >> 2; t ^= t >> 4; t ^= t >> 8; t ^= t >> 16;
            float2 a = shh[i];
            probs[t] = a.x * a.x + a.y * a.y;
        }
    } else {
        float4* __restrict__ dst4 = reinterpret_cast<float4*>(g_state[dstIdx]);
        for (int i2 = tid; i2 < 4096; i2 += 256) {
            unsigned v = i2 >> 1, cp = i2 & 1;
            dst4[(v << 10) | (f << 1) | cp] = sh4h[i2];
        }
    }
}

// ---------------------------------------------------------------------------
extern "C" void kernel_launch(void* const* d_in, const int* in_sizes, int n_in,
                              void* d_out, int out_size) {
    (void)in_sizes; (void)n_in; (void)out_size;
    const float* params = (const float*)d_in[0];
    float* out = (float*)d_out;

    cudaFuncSetAttribute(kernelH, cudaFuncAttributeMaxDynamicSharedMemorySize, 65536);

    prep_kernel<<<1, 1024>>>(params);

    // Layer 0 is folded into the product tables; layer-(l-1) CNOT chain is folded
    // into kernelL's Gray-code load; layer-7 chain is folded into the prob scatter.
    // Buffers: L always writes buf0; H reads buf0, writes buf1; L(l>=2) reads buf1.
    kernelL<<<2048, 256>>>(1, /*src*/1, /*dst*/0, /*first*/1);
    kernelH<<<512, 256, 65536>>>(1, 0, 1, nullptr);
    for (int l = 2; l <= 7; l++) {
        kernelL<<<2048, 256>>>(l, 1, 0, 0);
        kernelH<<<512, 256, 65536>>>(l, 0, 1, (l == 7) ? out : nullptr);
    }
}

// round 2
// speedup vs baseline: 1.5291x; 1.5291x over previous
#include <cuda_runtime.h>

#define NQ      22
#define NSTATE  (1u << NQ)
#define NLAYERS 8

typedef unsigned long long u64;

// Ping-pong statevector buffers (64 MB total; resident in L2)
__device__ float2 g_state[2][NSTATE];
// Fused single-qubit unitaries U = RX*RZ*RY (float2 form, for table build)
__device__ float2 g_U[NLAYERS][NQ][4];
// Packed duplicated coefficients for f32x2 math:
// [0]=dup(u00.re) [1]=dup(u00.im) [2]=dup(u01.re) [3]=dup(u01.im)
// [4]=dup(u10.re) [5]=dup(u10.im) [6]=dup(u11.re) [7]=dup(u11.im)
__device__ u64 g_Upk[NLAYERS][NQ][8];
// Product-state tables for layer 0: amp(g) = Phi[g>>11] * Plo[g & 0x7FF]
__device__ float2 g_Phi[2048];
__device__ float2 g_Plo[2048];

// ---------------------------------------------------------------------------
// f32x2 packed helpers (amplitude packed as (re, im) in a 64-bit reg pair)
// ---------------------------------------------------------------------------
__device__ __forceinline__ u64 pk2(float lo, float hi) {
    u64 r; asm("mov.b64 %0, {%1, %2};" : "=l"(r) : "f"(lo), "f"(hi)); return r;
}
__device__ __forceinline__ void unpk2(u64 v, float& lo, float& hi) {
    asm("mov.b64 {%0, %1}, %2;" : "=f"(lo), "=f"(hi) : "l"(v));
}
__device__ __forceinline__ u64 f2mul(u64 a, u64 b) {
    u64 r; asm("mul.rn.f32x2 %0, %1, %2;" : "=l"(r) : "l"(a), "l"(b)); return r;
}
__device__ __forceinline__ u64 f2fma(u64 a, u64 b, u64 c) {
    u64 r; asm("fma.rn.f32x2 %0, %1, %2, %3;" : "=l"(r) : "l"(a), "l"(b), "l"(c)); return r;
}
// (re, im) -> (-im, re)   [multiplying by i], sign flip on ALU pipe
__device__ __forceinline__ u64 sneg(u64 x) {
    float re, im; unpk2(x, re, im);
    unsigned nim = __float_as_uint(im) ^ 0x80000000u;
    u64 r; asm("mov.b64 %0, {%1, %2};" : "=l"(r) : "r"(nim), "r"(__float_as_uint(re)));
    return r;
}

struct GateP { u64 c00r, c00i, c01r, c01i, c10r, c10i, c11r, c11i; };

__device__ __forceinline__ GateP ldgate(const u64* __restrict__ p) {
    GateP G;
    G.c00r = __ldg(p + 0); G.c00i = __ldg(p + 1);
    G.c01r = __ldg(p + 2); G.c01i = __ldg(p + 3);
    G.c10r = __ldg(p + 4); G.c10i = __ldg(p + 5);
    G.c11r = __ldg(p + 6); G.c11i = __ldg(p + 7);
    return G;
}

// y0 = u00*x0 + u01*x1 ; y1 = u10*x0 + u11*x1   (2 MUL + 6 FMA f32x2)
__device__ __forceinline__ void bfly(const GateP& G, u64& x0, u64& x1) {
    u64 s0 = sneg(x0), s1 = sneg(x1);
    u64 y0 = f2mul(G.c00r, x0);
    y0 = f2fma(G.c00i, s0, y0);
    y0 = f2fma(G.c01r, x1, y0);
    y0 = f2fma(G.c01i, s1, y0);
    u64 y1 = f2mul(G.c10r, x0);
    y1 = f2fma(G.c10i, s0, y1);
    y1 = f2fma(G.c11r, x1, y1);
    y1 = f2fma(G.c11i, s1, y1);
    x0 = y0; x1 = y1;
}

// Apply one gate across register bit K of the 16-amp register file
template<int K>
__device__ __forceinline__ void gate_on_regbit(const u64* __restrict__ Uq, u64 a[16]) {
    GateP G = ldgate(Uq);
#pragma unroll
    for (int m = 0; m < 8; m++) {
        int j0 = ((m >> K) << (K + 1)) | (m & ((1 << K) - 1));
        bfly(G, a[j0], a[j0 | (1 << K)]);
    }
}

// Smem swizzle: <=2-way conflicts for all phase load/store patterns used below
__device__ __forceinline__ int SW(int i) { return i ^ ((i >> 4) & 15); }

// ---------------------------------------------------------------------------
// Prep: fused U matrices (float2 + packed), then layer-0 product tables.
// ---------------------------------------------------------------------------
__global__ void prep_kernel(const float* __restrict__ p) {
    int tid = threadIdx.x;
    if (tid < NLAYERS * NQ) {
        int l = tid / NQ, q = tid % NQ;
        float ty = p[l * 3 * NQ + q];
        float tz = p[l * 3 * NQ + NQ + q];
        float tx = p[l * 3 * NQ + 2 * NQ + q];
        float cy = cosf(0.5f * ty), sy = sinf(0.5f * ty);
        float cz = cosf(0.5f * tz), sz = sinf(0.5f * tz);
        float cx = cosf(0.5f * tx), sx = sinf(0.5f * tx);
        float2 em = make_float2(cz, -sz);
        float2 ep = make_float2(cz, sz);
        float2 u00 = make_float2(cx * cy * em.x + sx * sy * ep.y,
                                 cx * cy * em.y - sx * sy * ep.x);
        float2 u01 = make_float2(-cx * sy * em.x + sx * cy * ep.y,
                                 -cx * sy * em.y - sx * cy * ep.x);
        float2 u10 = make_float2(sx * cy * em.y + cx * sy * ep.x,
                                 -sx * cy * em.x + cx * sy * ep.y);
        float2 u11 = make_float2(-sx * sy * em.y + cx * cy * ep.x,
                                 sx * sy * em.x + cx * cy * ep.y);
        g_U[l][q][0] = u00; g_U[l][q][1] = u01;
        g_U[l][q][2] = u10; g_U[l][q][3] = u11;
        u64* pkd = g_Upk[l][q];
        pkd[0] = pk2(u00.x, u00.x); pkd[1] = pk2(u00.y, u00.y);
        pkd[2] = pk2(u01.x, u01.x); pkd[3] = pk2(u01.y, u01.y);
        pkd[4] = pk2(u10.x, u10.x); pkd[5] = pk2(u10.y, u10.y);
        pkd[6] = pk2(u11.x, u11.x); pkd[7] = pk2(u11.y, u11.y);
    }
    __syncthreads();
    for (int i = tid; i < 2048; i += blockDim.x) {
        float2 ph = make_float2(1.f, 0.f);
        float2 pl = make_float2(1.f, 0.f);
        for (int q = 0; q <= 10; q++) {
            int b = (i >> (10 - q)) & 1;
            float2 u = g_U[0][q][b * 2];
            ph = make_float2(ph.x * u.x - ph.y * u.y, ph.x * u.y + ph.y * u.x);
        }
        for (int q = 11; q <= 21; q++) {
            int b = (i >> (21 - q)) & 1;
            float2 u = g_U[0][q][b * 2];
            pl = make_float2(pl.x * u.x - pl.y * u.y, pl.x * u.y + pl.y * u.x);
        }
        g_Phi[i] = ph;
        g_Plo[i] = pl;
    }
}

// ---------------------------------------------------------------------------
// L kernel: tile = 8192 contiguous amps (bits 0..12), gates on qubits 9..21.
// Load folds previous layer's CNOT chain via gray addressing; first=1
// synthesizes the layer-0 product state. 4 register phases, 3 smem transposes.
// ---------------------------------------------------------------------------
__global__ void __launch_bounds__(512) kernelL(int layer, int srcIdx, int dstIdx, int first) {
    extern __shared__ u64 sh[];
    const int t = threadIdx.x;                 // 9 bits
    const unsigned h = blockIdx.x;             // global bits 13..21 (9 bits)
    const unsigned ghi = h ^ (h >> 1);
    const unsigned c12 = (h & 1u) << 12;
    const u64* __restrict__ Ul = &g_Upk[layer][0][0];
    u64 a[16];

    // ---- Phase A load: local i = (r<<9)|t ; reg bits = local 9..12
    if (first) {
#pragma unroll
        for (int r = 0; r < 16; r++) {
            unsigned i = (r << 9) | t;
            unsigned glo = (i ^ (i >> 1)) ^ c12;
            float2 ph = g_Phi[(ghi << 2) | (glo >> 11)];
            float2 pl = g_Plo[glo & 2047];
            a[r] = pk2(ph.x * pl.x - ph.y * pl.y, ph.x * pl.y + ph.y * pl.x);
        }
    } else {
        const float2* __restrict__ src = g_state[srcIdx] + ((size_t)ghi << 13);
#pragma unroll
        for (int r = 0; r < 16; r++) {
            unsigned i = (r << 9) | t;
            unsigned glo = (i ^ (i >> 1)) ^ c12;
            float2 v = __ldg(&src[glo]);
            a[r] = pk2(v.x, v.y);
        }
    }
    // local bit 9+k -> qubit 12-k
    gate_on_regbit<0>(Ul + 12 * 8, a);
    gate_on_regbit<1>(Ul + 11 * 8, a);
    gate_on_regbit<2>(Ul + 10 * 8, a);
    gate_on_regbit<3>(Ul + 9 * 8, a);
#pragma unroll
    for (int r = 0; r < 16; r++) sh[SW((r << 9) | t)] = a[r];
    __syncthreads();

    // ---- Phase B: i = (w<<9)|(r<<5)|l ; reg bits = local 5..8 -> qubits 16-k
    const int w = t >> 5, l = t & 31;
#pragma unroll
    for (int r = 0; r < 16; r++) a[r] = sh[SW((w << 9) | (r << 5) | l)];
    gate_on_regbit<0>(Ul + 16 * 8, a);
    gate_on_regbit<1>(Ul + 15 * 8, a);
    gate_on_regbit<2>(Ul + 14 * 8, a);
    gate_on_regbit<3>(Ul + 13 * 8, a);
#pragma unroll
    for (int r = 0; r < 16; r++) sh[SW((w << 9) | (r << 5) | l)] = a[r];
    __syncthreads();

    // ---- Phase C: i = (t<<4)|r ; reg bits = local 0..3 -> qubits 21-k
#pragma unroll
    for (int r = 0; r < 16; r++) a[r] = sh[SW((t << 4) | r)];
    gate_on_regbit<0>(Ul + 21 * 8, a);
    gate_on_regbit<1>(Ul + 20 * 8, a);
    gate_on_regbit<2>(Ul + 19 * 8, a);
    gate_on_regbit<3>(Ul + 18 * 8, a);
#pragma unroll
    for (int r = 0; r < 16; r++) sh[SW((t << 4) | r)] = a[r];
    __syncthreads();

    // ---- Phase D: i = (hi5<<8)|(r<<4)|lo4 ; reg bit 0 = local 4 -> qubit 17
    const int hi5 = t >> 4, lo4 = t & 15;
#pragma unroll
    for (int r = 0; r < 16; r++) a[r] = sh[SW((hi5 << 8) | (r << 4) | lo4)];
    gate_on_regbit<0>(Ul + 17 * 8, a);

    float2* __restrict__ dst = g_state[dstIdx] + ((size_t)h << 13);
#pragma unroll
    for (int r = 0; r < 16; r++) {
        float re, im; unpk2(a[r], re, im);
        dst[(hi5 << 8) | (r << 4) | lo4] = make_float2(re, im);
    }
}

// ---------------------------------------------------------------------------
// H kernel: tile bits {0..3} U {13..21} (8192 amps), gates on qubits 0..8.
// Global accesses are 128B-contiguous chunks. Optionally folds final CNOT
// chain + |amp|^2 into the store (probs != nullptr). 3 phases, 2 transposes.
// ---------------------------------------------------------------------------
__global__ void __launch_bounds__(512) kernelH(int layer, int srcIdx, int dstIdx,
                                               float* __restrict__ probs) {
    extern __shared__ u64 sh[];
    const int t = threadIdx.x;                 // 9 bits
    const unsigned f = blockIdx.x;             // global bits 4..12 (9 bits)
    const u64* __restrict__ Ul = &g_Upk[layer][0][0];
    u64 a[16];

    // ---- Phase A: local i = (r<<9)|t ; global j = ((i>>4)<<13)|(f<<4)|(i&15)
    const unsigned tpart = ((t >> 4) << 13) | (f << 4) | (t & 15);
    {
        const float2* __restrict__ src = g_state[srcIdx];
#pragma unroll
        for (int r = 0; r < 16; r++) {
            float2 v = __ldg(&src[tpart | (r << 18)]);
            a[r] = pk2(v.x, v.y);
        }
    }
    // local bit 9+k = global bit 18+k -> qubit 3-k
    gate_on_regbit<0>(Ul + 3 * 8, a);
    gate_on_regbit<1>(Ul + 2 * 8, a);
    gate_on_regbit<2>(Ul + 1 * 8, a);
    gate_on_regbit<3>(Ul + 0 * 8, a);
#pragma unroll
    for (int r = 0; r < 16; r++) sh[SW((r << 9) | t)] = a[r];
    __syncthreads();

    // ---- Phase B: i = (w<<9)|(r<<5)|l ; local bit 5+k -> qubit 7-k
    const int w = t >> 5, l = t & 31;
#pragma unroll
    for (int r = 0; r < 16; r++) a[r] = sh[SW((w << 9) | (r << 5) | l)];
    gate_on_regbit<0>(Ul + 7 * 8, a);
    gate_on_regbit<1>(Ul + 6 * 8, a);
    gate_on_regbit<2>(Ul + 5 * 8, a);
    gate_on_regbit<3>(Ul + 4 * 8, a);
#pragma unroll
    for (int r = 0; r < 16; r++) sh[SW((w << 9) | (r << 5) | l)] = a[r];
    __syncthreads();

    // ---- Phase C: i = (hi5<<8)|(r<<4)|lo4 ; reg bit 0 = local 4 -> qubit 8
    const int hi5 = t >> 4, lo4 = t & 15;
#pragma unroll
    for (int r = 0; r < 16; r++) a[r] = sh[SW((hi5 << 8) | (r << 4) | lo4)];
    gate_on_regbit<0>(Ul + 8 * 8, a);

    // global j for phase-C layout: j = (hi5<<17)|(r<<13)|(f<<4)|lo4
    const unsigned tpart2 = ((unsigned)hi5 << 17) | (f << 4) | (unsigned)lo4;
    if (probs) {
#pragma unroll
        for (int r = 0; r < 16; r++) {
            unsigned j = tpart2 | (r << 13);
            unsigned o = j;
            o ^= o >> 1; o ^= o >> 2; o ^= o >> 4; o ^= o >> 8; o ^= o >> 16;
            float re, im; unpk2(a[r], re, im);
            probs[o] = fmaf(re, re, im * im);
        }
    } else {
        float2* __restrict__ dst = g_state[dstIdx];
#pragma unroll
        for (int r = 0; r < 16; r++) {
            float re, im; unpk2(a[r], re, im);
            dst[tpart2 | (r << 13)] = make_float2(re, im);
        }
    }
}

// ---------------------------------------------------------------------------
extern "C" void kernel_launch(void* const* d_in, const int* in_sizes, int n_in,
                              void* d_out, int out_size) {
    (void)in_sizes; (void)n_in; (void)out_size;
    const float* params = (const float*)d_in[0];
    float* out = (float*)d_out;

    cudaFuncSetAttribute(kernelL, cudaFuncAttributeMaxDynamicSharedMemorySize, 65536);
    cudaFuncSetAttribute(kernelH, cudaFuncAttributeMaxDynamicSharedMemorySize, 65536);

    prep_kernel<<<1, 1024>>>(params);

    // Layer 0 folded into tables; layer-(l-1) CNOT chain folded into L's gray
    // load; layer-7 chain folded into the prob scatter.
    kernelL<<<512, 512, 65536>>>(1, /*src*/1, /*dst*/0, /*first*/1);
    kernelH<<<512, 512, 65536>>>(1, 0, 1, nullptr);
    for (int ll = 2; ll <= 7; ll++) {
        kernelL<<<512, 512, 65536>>>(ll, 1, 0, 0);
        kernelH<<<512, 512, 65536>>>(ll, 0, 1, (ll == 7) ? out : nullptr);
    }
}

// round 4
// speedup vs baseline: 1.7654x; 1.1546x over previous
#include <cuda_runtime.h>

#define NQ      22
#define NSTATE  (1u << NQ)
#define NLAYERS 8

typedef unsigned long long u64;

// Ping-pong statevector buffers (64 MB total; resident in L2)
__device__ float2 g_state[2][NSTATE];
// Fused single-qubit unitaries U = RX*RZ*RY (float2 form, for table build)
__device__ float2 g_U[NLAYERS][NQ][4];
// Packed duplicated coefficients for f32x2 math
__device__ u64 g_Upk[NLAYERS][NQ][8];
// Product-state tables for layer 0: amp(g) = Phi[g>>11] * Plo[g & 0x7FF]
__device__ float2 g_Phi[2048];
__device__ float2 g_Plo[2048];

// ---------------------------------------------------------------------------
// f32x2 packed helpers (amplitude packed as (re, im) in a 64-bit reg pair)
// ---------------------------------------------------------------------------
__device__ __forceinline__ u64 pk2(float lo, float hi) {
    u64 r; asm("mov.b64 %0, {%1, %2};" : "=l"(r) : "f"(lo), "f"(hi)); return r;
}
__device__ __forceinline__ void unpk2(u64 v, float& lo, float& hi) {
    asm("mov.b64 {%0, %1}, %2;" : "=f"(lo), "=f"(hi) : "l"(v));
}
__device__ __forceinline__ u64 f2mul(u64 a, u64 b) {
    u64 r; asm("mul.rn.f32x2 %0, %1, %2;" : "=l"(r) : "l"(a), "l"(b)); return r;
}
__device__ __forceinline__ u64 f2fma(u64 a, u64 b, u64 c) {
    u64 r; asm("fma.rn.f32x2 %0, %1, %2, %3;" : "=l"(r) : "l"(a), "l"(b), "l"(c)); return r;
}
// (re, im) -> (-im, re)
__device__ __forceinline__ u64 sneg(u64 x) {
    float re, im; unpk2(x, re, im);
    unsigned nim = __float_as_uint(im) ^ 0x80000000u;
    u64 r; asm("mov.b64 %0, {%1, %2};" : "=l"(r) : "r"(nim), "r"(__float_as_uint(re)));
    return r;
}

struct GateP { u64 c00r, c00i, c01r, c01i, c10r, c10i, c11r, c11i; };

__device__ __forceinline__ GateP ldgate(const u64* __restrict__ p) {
    GateP G;
    G.c00r = __ldg(p + 0); G.c00i = __ldg(p + 1);
    G.c01r = __ldg(p + 2); G.c01i = __ldg(p + 3);
    G.c10r = __ldg(p + 4); G.c10i = __ldg(p + 5);
    G.c11r = __ldg(p + 6); G.c11i = __ldg(p + 7);
    return G;
}

// y0 = u00*x0 + u01*x1 ; y1 = u10*x0 + u11*x1   (2 MUL + 6 FMA f32x2)
__device__ __forceinline__ void bfly(const GateP& G, u64& x0, u64& x1) {
    u64 s0 = sneg(x0), s1 = sneg(x1);
    u64 y0 = f2mul(G.c00r, x0);
    y0 = f2fma(G.c00i, s0, y0);
    y0 = f2fma(G.c01r, x1, y0);
    y0 = f2fma(G.c01i, s1, y0);
    u64 y1 = f2mul(G.c10r, x0);
    y1 = f2fma(G.c10i, s0, y1);
    y1 = f2fma(G.c11r, x1, y1);
    y1 = f2fma(G.c11i, s1, y1);
    x0 = y0; x1 = y1;
}

// Apply one gate across register bit K of the 16-amp register file
template<int K>
__device__ __forceinline__ void gate_on_regbit(const u64* __restrict__ Uq, u64 a[16]) {
    GateP G = ldgate(Uq);
#pragma unroll
    for (int m = 0; m < 8; m++) {
        int j0 = ((m >> K) << (K + 1)) | (m & ((1 << K) - 1));
        bfly(G, a[j0], a[j0 | (1 << K)]);
    }
}

// Swizzles (verified conflict-free / half-warp-only for each kernel's patterns)
__device__ __forceinline__ int SWL(int i) { return i ^ ((i >> 4) & 15); }   // kernelL
__device__ __forceinline__ int SWH(int i) { return i ^ ((i >> 2) & 24); }   // kernelH

// ---------------------------------------------------------------------------
// Prep: fused U matrices (float2 + packed), then layer-0 product tables.
// ---------------------------------------------------------------------------
__global__ void prep_kernel(const float* __restrict__ p) {
    int tid = threadIdx.x;
    if (tid < NLAYERS * NQ) {
        int l = tid / NQ, q = tid % NQ;
        float ty = p[l * 3 * NQ + q];
        float tz = p[l * 3 * NQ + NQ + q];
        float tx = p[l * 3 * NQ + 2 * NQ + q];
        float cy = cosf(0.5f * ty), sy = sinf(0.5f * ty);
        float cz = cosf(0.5f * tz), sz = sinf(0.5f * tz);
        float cx = cosf(0.5f * tx), sx = sinf(0.5f * tx);
        float2 em = make_float2(cz, -sz);
        float2 ep = make_float2(cz, sz);
        float2 u00 = make_float2(cx * cy * em.x + sx * sy * ep.y,
                                 cx * cy * em.y - sx * sy * ep.x);
        float2 u01 = make_float2(-cx * sy * em.x + sx * cy * ep.y,
                                 -cx * sy * em.y - sx * cy * ep.x);
        float2 u10 = make_float2(sx * cy * em.y + cx * sy * ep.x,
                                 -sx * cy * em.x + cx * sy * ep.y);
        float2 u11 = make_float2(-sx * sy * em.y + cx * cy * ep.x,
                                 sx * sy * em.x + cx * cy * ep.y);
        g_U[l][q][0] = u00; g_U[l][q][1] = u01;
        g_U[l][q][2] = u10; g_U[l][q][3] = u11;
        u64* pkd = g_Upk[l][q];
        pkd[0] = pk2(u00.x, u00.x); pkd[1] = pk2(u00.y, u00.y);
        pkd[2] = pk2(u01.x, u01.x); pkd[3] = pk2(u01.y, u01.y);
        pkd[4] = pk2(u10.x, u10.x); pkd[5] = pk2(u10.y, u10.y);
        pkd[6] = pk2(u11.x, u11.x); pkd[7] = pk2(u11.y, u11.y);
    }
    __syncthreads();
    for (int i = tid; i < 2048; i += blockDim.x) {
        float2 ph = make_float2(1.f, 0.f);
        float2 pl = make_float2(1.f, 0.f);
        for (int q = 0; q <= 10; q++) {
            int b = (i >> (10 - q)) & 1;
            float2 u = g_U[0][q][b * 2];
            ph = make_float2(ph.x * u.x - ph.y * u.y, ph.x * u.y + ph.y * u.x);
        }
        for (int q = 11; q <= 21; q++) {
            int b = (i >> (21 - q)) & 1;
            float2 u = g_U[0][q][b * 2];
            pl = make_float2(pl.x * u.x - pl.y * u.y, pl.x * u.y + pl.y * u.x);
        }
        g_Phi[i] = ph;
        g_Plo[i] = pl;
    }
}

// ---------------------------------------------------------------------------
// L kernel: tile = 8192 contiguous amps (bits 0..12), 12 gates on bits 0..11
// (qubits 10..21). Load folds previous layer's CNOT chain via gray addressing;
// first=1 synthesizes the layer-0 product state. 3 phases, 2 smem transposes.
// ---------------------------------------------------------------------------
__global__ void __launch_bounds__(512, 2) kernelL(int layer, int srcIdx, int dstIdx, int first) {
    extern __shared__ u64 sh[];
    const int t = threadIdx.x;                 // 9 bits
    const unsigned h = blockIdx.x;             // global bits 13..21 (9 bits)
    const unsigned ghi = h ^ (h >> 1);
    const unsigned c12 = (h & 1u) << 12;
    const u64* __restrict__ Ul = &g_Upk[layer][0][0];
    u64 a[16];

    const int b12 = t >> 8, t8 = t & 255;
    // ---- Phase A: i = (b12<<12)|(r<<8)|t8 ; reg bits local 8..11 -> qubit 13-k
    if (first) {
#pragma unroll
        for (int r = 0; r < 16; r++) {
            unsigned i = (b12 << 12) | (r << 8) | t8;
            unsigned glo = (i ^ (i >> 1)) ^ c12;
            float2 ph = g_Phi[(ghi << 2) | (glo >> 11)];
            float2 pl = g_Plo[glo & 2047];
            a[r] = pk2(ph.x * pl.x - ph.y * pl.y, ph.x * pl.y + ph.y * pl.x);
        }
    } else {
        const float2* __restrict__ src = g_state[srcIdx] + ((size_t)ghi << 13);
#pragma unroll
        for (int r = 0; r < 16; r++) {
            unsigned i = (b12 << 12) | (r << 8) | t8;
            unsigned glo = (i ^ (i >> 1)) ^ c12;
            float2 v = __ldg(&src[glo]);
            a[r] = pk2(v.x, v.y);
        }
    }
    gate_on_regbit<0>(Ul + 13 * 8, a);
    gate_on_regbit<1>(Ul + 12 * 8, a);
    gate_on_regbit<2>(Ul + 11 * 8, a);
    gate_on_regbit<3>(Ul + 10 * 8, a);
#pragma unroll
    for (int r = 0; r < 16; r++) sh[SWL((b12 << 12) | (r << 8) | t8)] = a[r];
    __syncthreads();

    // ---- Phase B: i = (t<<4)|r ; reg bits local 0..3 -> qubit 21-k
#pragma unroll
    for (int r = 0; r < 16; r++) a[r] = sh[SWL((t << 4) | r)];
    gate_on_regbit<0>(Ul + 21 * 8, a);
    gate_on_regbit<1>(Ul + 20 * 8, a);
    gate_on_regbit<2>(Ul + 19 * 8, a);
    gate_on_regbit<3>(Ul + 18 * 8, a);
#pragma unroll
    for (int r = 0; r < 16; r++) sh[SWL((t << 4) | r)] = a[r];
    __syncthreads();

    // ---- Phase C: i = (hi5<<8)|(r<<4)|lo4 ; reg bits local 4..7 -> qubit 17-k
    const int hi5 = t >> 4, lo4 = t & 15;
#pragma unroll
    for (int r = 0; r < 16; r++) a[r] = sh[SWL((hi5 << 8) | (r << 4) | lo4)];
    gate_on_regbit<0>(Ul + 17 * 8, a);
    gate_on_regbit<1>(Ul + 16 * 8, a);
    gate_on_regbit<2>(Ul + 15 * 8, a);
    gate_on_regbit<3>(Ul + 14 * 8, a);

    float2* __restrict__ dst = g_state[dstIdx] + ((size_t)h << 13);
#pragma unroll
    for (int r = 0; r < 16; r++) {
        float re, im; unpk2(a[r], re, im);
        dst[(hi5 << 8) | (r << 4) | lo4] = make_float2(re, im);
    }
}

// ---------------------------------------------------------------------------
// H kernel: tile bits {0..2} U {12..21} (8192 amps), 10 gates on global bits
// 12..21 (qubits 0..9). blockIdx = global bits 3..11. Optionally folds final
// CNOT chain + |amp|^2 into the store (probs != nullptr). 3 phases.
// Local map: local 0..2 = global 0..2, local 3..12 = global 12..21.
// j(i) = ((i>>3)<<12) | (f<<3) | (i&7)
// ---------------------------------------------------------------------------
__global__ void __launch_bounds__(512, 2) kernelH(int layer, int srcIdx, int dstIdx,
                                                  float* __restrict__ probs) {
    extern __shared__ u64 sh[];
    const int t = threadIdx.x;                 // 9 bits
    const unsigned f = blockIdx.x;             // global bits 3..11 (9 bits)
    const u64* __restrict__ Ul = &g_Upk[layer][0][0];
    u64 a[16];

    // ---- Phase A: i = (r<<9)|t ; reg bits local 9..12 = global 18..21 -> qubit 3-k
    const unsigned jt = ((unsigned)(t >> 3) << 12) | (f << 3) | (unsigned)(t & 7);
    {
        const float2* __restrict__ src = g_state[srcIdx];
#pragma unroll
        for (int r = 0; r < 16; r++) {
            float2 v = __ldg(&src[jt | (r << 18)]);
            a[r] = pk2(v.x, v.y);
        }
    }
    gate_on_regbit<0>(Ul + 3 * 8, a);
    gate_on_regbit<1>(Ul + 2 * 8, a);
    gate_on_regbit<2>(Ul + 1 * 8, a);
    gate_on_regbit<3>(Ul + 0 * 8, a);
#pragma unroll
    for (int r = 0; r < 16; r++) sh[SWH((r << 9) | t)] = a[r];
    __syncthreads();

    // ---- Phase B: i = (hi4<<9)|(r<<5)|lo5 ; local 5..8 = global 14..17 -> qubit 7-k
    const int hi4 = t >> 5, lo5 = t & 31;
#pragma unroll
    for (int r = 0; r < 16; r++) a[r] = sh[SWH((hi4 << 9) | (r << 5) | lo5)];
    gate_on_regbit<0>(Ul + 7 * 8, a);
    gate_on_regbit<1>(Ul + 6 * 8, a);
    gate_on_regbit<2>(Ul + 5 * 8, a);
    gate_on_regbit<3>(Ul + 4 * 8, a);
#pragma unroll
    for (int r = 0; r < 16; r++) sh[SWH((hi4 << 9) | (r << 5) | lo5)] = a[r];
    __syncthreads();

    // ---- Phase C: reg bits: r0,r1 -> local 3,4 (qubits 9,8); r2,r3 -> local 9,10
    // i = (t_c<<11)|(rf<<9)|(t_b<<5)|(rg<<3)|t_a
    const int t_a = t & 7, t_b = (t >> 3) & 15, t_c = t >> 7;
#pragma unroll
    for (int r = 0; r < 16; r++) {
        int i = (t_c << 11) | ((r >> 2) << 9) | (t_b << 5) | ((r & 3) << 3) | t_a;
        a[r] = sh[SWH(i)];
    }
    gate_on_regbit<0>(Ul + 9 * 8, a);      // local 3 = global 12 -> qubit 9
    gate_on_regbit<1>(Ul + 8 * 8, a);      // local 4 = global 13 -> qubit 8

    if (probs) {
#pragma unroll
        for (int r = 0; r < 16; r++) {
            int i = (t_c << 11) | ((r >> 2) << 9) | (t_b << 5) | ((r & 3) << 3) | t_a;
            unsigned j = (((unsigned)i >> 3) << 12) | (f << 3) | (unsigned)(i & 7);
            unsigned o = j;
            o ^= o >> 1; o ^= o >> 2; o ^= o >> 4; o ^= o >> 8; o ^= o >> 16;
            float re, im; unpk2(a[r], re, im);
            probs[o] = fmaf(re, re, im * im);
        }
    } else {
        float2* __restrict__ dst = g_state[dstIdx];
#pragma unroll
        for (int r = 0; r < 16; r++) {
            int i = (t_c << 11) | ((r >> 2) << 9) | (t_b << 5) | ((r & 3) << 3) | t_a;
            unsigned j = (((unsigned)i >> 3) << 12) | (f << 3) | (unsigned)(i & 7);
            float re, im; unpk2(a[r], re, im);
            dst[j] = make_float2(re, im);
        }
    }
}

// ---------------------------------------------------------------------------
extern "C" void kernel_launch(void* const* d_in, const int* in_sizes, int n_in,
                              void* d_out, int out_size) {
    (void)in_sizes; (void)n_in; (void)out_size;
    const float* params = (const float*)d_in[0];
    float* out = (float*)d_out;

    cudaFuncSetAttribute(kernelL, cudaFuncAttributeMaxDynamicSharedMemorySize, 65536);
    cudaFuncSetAttribute(kernelH, cudaFuncAttributeMaxDynamicSharedMemorySize, 65536);

    prep_kernel<<<1, 1024>>>(params);

    // Layer 0 folded into tables; layer-(l-1) CNOT chain folded into L's gray
    // load; layer-7 chain folded into the prob scatter.
    kernelL<<<512, 512, 65536>>>(1, /*src*/1, /*dst*/0, /*first*/1);
    kernelH<<<512, 512, 65536>>>(1, 0, 1, nullptr);
    for (int ll = 2; ll <= 7; ll++) {
        kernelL<<<512, 512, 65536>>>(ll, 1, 0, 0);
        kernelH<<<512, 512, 65536>>>(ll, 0, 1, (ll == 7) ? out : nullptr);
    }
}